// round 4
// baseline (speedup 1.0000x reference)
#include <cuda_runtime.h>
#include <cuda_fp16.h>
#include <stdint.h>

// Problem constants
#define B_   64
#define C_   2048
#define D_   512
#define M_   128
#define T_   100
#define NN_  1920
#define SPL  2          // splits of the non-muc rows per batch (128 CTAs = 1 wave)
#define RPS  960        // rows per split
#define TR   16         // non rows per tile
#define NT   60         // tiles per split

// Scratch (device globals; no allocation allowed)
__device__ __align__(16) __half g_mucH[(size_t)B_ * M_ * D_];    // RAW muc rows, fp16 (GEMM operand)
__device__ __align__(16) float  g_mucN[(size_t)B_ * M_ * D_];    // normalized muc rows, fp32 (loss)
__device__ float g_nonInv[B_ * NN_];                             // 1/max(||raw non row||,1e-12)
__device__ float g_partMax[B_ * SPL * M_];
__device__ int   g_partIdx[B_ * SPL * M_];
__device__ float g_trip[B_ * T_];

// ---------------------------------------------------------------------------
// Kernel 1: muc-only gather. One warp per (b, j) muc row.
// Writes raw fp16 (GEMM operand) and normalized fp32 (loss operand).
// ---------------------------------------------------------------------------
__global__ void __launch_bounds__(256) prep_kernel(const float* __restrict__ emb,
                                                   const int* __restrict__ muc_idx) {
  int lane = threadIdx.x & 31;
  int r = blockIdx.x * 8 + (threadIdx.x >> 5);   // [0, B_*M_)
  int b = r >> 7;
  int j = r & 127;
  int src = muc_idx[b * M_ + j];

  const float4* p = (const float4*)(emb + ((size_t)b * C_ + src) * D_);
  float4 v[4];
  float ss = 0.f;
#pragma unroll
  for (int i = 0; i < 4; i++) {
    v[i] = p[lane + i * 32];
    ss += v[i].x * v[i].x + v[i].y * v[i].y + v[i].z * v[i].z + v[i].w * v[i].w;
  }
#pragma unroll
  for (int d = 16; d; d >>= 1) ss += __shfl_xor_sync(0xffffffffu, ss, d);
  float inv = 1.0f / fmaxf(sqrtf(ss), 1e-12f);

  float4* dn = (float4*)(g_mucN + ((size_t)b * M_ + j) * D_);
  uint2*  dh = (uint2*)(g_mucH + ((size_t)b * M_ + j) * D_);
#pragma unroll
  for (int i = 0; i < 4; i++) {
    float4 w = v[i];
    // raw fp16 for the GEMM (anchor norm is argmax-invariant)
    __half2 h0 = __floats2half2_rn(w.x, w.y);
    __half2 h1 = __floats2half2_rn(w.z, w.w);
    uint2 u; u.x = *(unsigned*)&h0; u.y = *(unsigned*)&h1;
    dh[lane + i * 32] = u;
    // normalized fp32 for the loss
    w.x *= inv; w.y *= inv; w.z *= inv; w.w *= inv;
    dn[lane + i * 32] = w;
  }
}

// ---------------------------------------------------------------------------
// Kernel 2: fused gather + normalize + GEMM + argmax hard-negative mining.
// Block (s, b): 128 raw-fp16 anchors resident in smem; raw fp32 non rows
// streamed (gathered via non_idx) in 16-row double-buffered tiles, converted
// fp32->fp16 in-SMEM with on-the-fly 1/||n|| computation; mma.sync HMMA;
// per-column invn scaling applied at the accumulator epilogue.
// ---------------------------------------------------------------------------
__device__ __forceinline__ uint32_t swz(uint32_t base, int row, int chunk) {
  // fp16 row stride = 1024B; 16B chunks xor-swizzled by row%8
  return base + (uint32_t)(row << 10) + (uint32_t)(((chunk ^ (row & 7)) << 4));
}

__device__ __forceinline__ void cpasync16(uint32_t dst, const void* src) {
  asm volatile("cp.async.cg.shared.global [%0], [%1], 16;\n"
               :: "r"(dst), "l"(__cvta_generic_to_global(src)) : "memory");
}

__device__ __forceinline__ void ldsm4(uint32_t* r, uint32_t addr) {
  asm volatile("ldmatrix.sync.aligned.m8n8.x4.shared.b16 {%0,%1,%2,%3}, [%4];\n"
               : "=r"(r[0]), "=r"(r[1]), "=r"(r[2]), "=r"(r[3]) : "r"(addr));
}

__device__ __forceinline__ void mma16816(float* c, const uint32_t* a, uint32_t b0, uint32_t b1) {
  asm volatile("mma.sync.aligned.m16n8k16.row.col.f32.f16.f16.f32 "
               "{%0,%1,%2,%3}, {%4,%5,%6,%7}, {%8,%9}, {%0,%1,%2,%3};\n"
               : "+f"(c[0]), "+f"(c[1]), "+f"(c[2]), "+f"(c[3])
               : "r"(a[0]), "r"(a[1]), "r"(a[2]), "r"(a[3]), "r"(b0), "r"(b1));
}

// SMEM layout (bytes):
//   sA   : 0          .. 131072   anchors fp16 (128 x 512, swizzled)
//   sF32 : 131072     .. 196608   fp32 tile double-buffer (2 x 16 x 2048B, linear)
//   sH   : 196608     .. 229376   fp16 tile double-buffer (2 x 16 x 1024B, swizzled)
//   sInv : 229376     .. 229504   invn per tile row (2 x 16 floats)
#define OFF_F32 131072u
#define OFF_H   196608u
#define OFF_INV 229376u
#define SMEM_SZ 229504

__global__ void __launch_bounds__(256, 1) mine_kernel(const float* __restrict__ emb,
                                                      const int* __restrict__ non_idx) {
  extern __shared__ char smem[];
  uint32_t sbase = (uint32_t)__cvta_generic_to_shared(smem);
  const uint32_t sA = sbase;

  int s = blockIdx.x, b = blockIdx.y;
  int tid = threadIdx.x, lane = tid & 31, w = tid >> 5;
  const __half* gA = g_mucH + (size_t)b * M_ * D_;
  const int* nidx = non_idx + b * NN_ + s * RPS;
  float* sInvF = (float*)(smem + OFF_INV);

  // ---- prologue: anchors + tile0 (group 0), tile1 (group 1) ----
#pragma unroll
  for (int i = 0; i < 32; i++) {
    int idx = tid + i * 256, row = idx >> 6, c = idx & 63;
    cpasync16(swz(sA, row, c), gA + (size_t)row * D_ + c * 8);
  }
  {
    int row = tid >> 4, cbase = (tid & 15) * 8;
    const float* src0 = emb + ((size_t)b * C_ + nidx[row]) * D_;
    uint32_t d0 = sbase + OFF_F32 + (uint32_t)(row * 2048);
#pragma unroll
    for (int i = 0; i < 8; i++) cpasync16(d0 + (cbase + i) * 16, src0 + (cbase + i) * 4);
    asm volatile("cp.async.commit_group;\n" ::: "memory");
    const float* src1 = emb + ((size_t)b * C_ + nidx[TR + row]) * D_;
    uint32_t d1 = sbase + OFF_F32 + 32768u + (uint32_t)(row * 2048);
#pragma unroll
    for (int i = 0; i < 8; i++) cpasync16(d1 + (cbase + i) * 16, src1 + (cbase + i) * 4);
    asm volatile("cp.async.commit_group;\n" ::: "memory");
  }

  float bv0 = -1e30f, bv1 = -1e30f;
  int bi0 = 0, bi1 = 0;

  const int arow = w * 16 + (lane & 15);
  const int brow = ((lane >> 4) << 3) + (lane & 7);
  const int bsel = (lane >> 3) & 1;

  for (int tile = 0; tile < NT; tile++) {
    int buf = tile & 1;
    if (tile < NT - 1) asm volatile("cp.async.wait_group 1;\n" ::: "memory");
    else               asm volatile("cp.async.wait_group 0;\n" ::: "memory");
    __syncthreads();

    // ---- convert fp32 -> fp16 (swizzled), compute 1/||row|| ----
    {
      const char* f32b = smem + OFF_F32 + buf * 32768;
      uint32_t hB = sbase + OFF_H + (uint32_t)(buf * 16384);
#pragma unroll
      for (int rr = 0; rr < 2; rr++) {
        int row = w * 2 + rr;
        const float4* rp = (const float4*)(f32b + row * 2048);
        float4 v[4]; float ss = 0.f;
#pragma unroll
        for (int i = 0; i < 4; i++) {
          v[i] = rp[lane + i * 32];
          ss += v[i].x * v[i].x + v[i].y * v[i].y + v[i].z * v[i].z + v[i].w * v[i].w;
        }
#pragma unroll
        for (int i = 0; i < 4; i++) {
          __half2 h0 = __floats2half2_rn(v[i].x, v[i].y);
          __half2 h1 = __floats2half2_rn(v[i].z, v[i].w);
          uint2 u; u.x = *(unsigned*)&h0; u.y = *(unsigned*)&h1;
          int chunk = (lane >> 1) + i * 16;
          *(uint2*)(smem + (swz(hB, row, chunk) - sbase) + (lane & 1) * 8) = u;
        }
#pragma unroll
        for (int d = 16; d; d >>= 1) ss += __shfl_xor_sync(0xffffffffu, ss, d);
        if (lane == 0) {
          float inv = 1.0f / fmaxf(sqrtf(ss), 1e-12f);
          sInvF[buf * 16 + row] = inv;
          g_nonInv[b * NN_ + s * RPS + tile * TR + row] = inv;
        }
      }
    }
    __syncthreads();

    // ---- prefetch tile+2 into the fp32 buffer just freed ----
    if (tile + 2 < NT) {
      int row = tid >> 4, cbase = (tid & 15) * 8;
      const float* src = emb + ((size_t)b * C_ + nidx[(tile + 2) * TR + row]) * D_;
      uint32_t dst = sbase + OFF_F32 + (uint32_t)(buf * 32768) + (uint32_t)(row * 2048);
#pragma unroll
      for (int i = 0; i < 8; i++) cpasync16(dst + (cbase + i) * 16, src + (cbase + i) * 4);
      asm volatile("cp.async.commit_group;\n" ::: "memory");
    }

    // ---- MMA: 128 anchors x 16 non rows x K=512 ----
    uint32_t hB = sbase + OFF_H + (uint32_t)(buf * 16384);
    float acc[8];
#pragma unroll
    for (int i = 0; i < 8; i++) acc[i] = 0.f;
#pragma unroll
    for (int ks = 0; ks < 32; ks++) {
      uint32_t a[4], bf[4];
      ldsm4(a,  swz(sA, arow, ks * 2 + (lane >> 4)));
      ldsm4(bf, swz(hB, brow, ks * 2 + bsel));
      mma16816(acc + 0, a, bf[0], bf[1]);   // cols 0..7
      mma16816(acc + 4, a, bf[2], bf[3]);   // cols 8..15
    }

    // ---- scale by invn and fold into running argmax ----
    int colBase = s * RPS + tile * TR + ((lane & 3) << 1);
#pragma unroll
    for (int f = 0; f < 2; f++) {
      int cl = f * 8 + ((lane & 3) << 1);           // column within tile
      float i0 = sInvF[buf * 16 + cl];
      float i1 = sInvF[buf * 16 + cl + 1];
      int c = colBase + f * 8;
      float v;
      v = acc[f * 4 + 0] * i0; if (v > bv0 || (v == bv0 && c     < bi0)) { bv0 = v; bi0 = c; }
      v = acc[f * 4 + 1] * i1; if (v > bv0 || (v == bv0 && c + 1 < bi0)) { bv0 = v; bi0 = c + 1; }
      v = acc[f * 4 + 2] * i0; if (v > bv1 || (v == bv1 && c     < bi1)) { bv1 = v; bi1 = c; }
      v = acc[f * 4 + 3] * i1; if (v > bv1 || (v == bv1 && c + 1 < bi1)) { bv1 = v; bi1 = c + 1; }
    }
  }

  // Combine the 4 lanes that share each output row
#pragma unroll
  for (int d = 1; d < 4; d <<= 1) {
    float ov = __shfl_xor_sync(0xffffffffu, bv0, d);
    int   oi = __shfl_xor_sync(0xffffffffu, bi0, d);
    if (ov > bv0 || (ov == bv0 && oi < bi0)) { bv0 = ov; bi0 = oi; }
    ov = __shfl_xor_sync(0xffffffffu, bv1, d);
    oi = __shfl_xor_sync(0xffffffffu, bi1, d);
    if (ov > bv1 || (ov == bv1 && oi < bi1)) { bv1 = ov; bi1 = oi; }
  }
  if ((lane & 3) == 0) {
    int g = lane >> 2;
    int o = (b * SPL + s) * M_ + w * 16 + g;
    g_partMax[o] = bv0; g_partIdx[o] = bi0;
    g_partMax[o + 8] = bv1; g_partIdx[o + 8] = bi1;
  }
}

// ---------------------------------------------------------------------------
// Kernel 3: per-triplet loss. One warp per (b, t).
// ---------------------------------------------------------------------------
__global__ void __launch_bounds__(256) loss_kernel(const float* __restrict__ emb,
                                                   const int* __restrict__ non_idx,
                                                   const int* __restrict__ anchor_idx,
                                                   const int* __restrict__ pos_idx) {
  int lane = threadIdx.x & 31;
  int trip = blockIdx.x * 8 + (threadIdx.x >> 5);  // [0, B_*T_)
  int b = trip / T_, t = trip - b * T_;
  int a = anchor_idx[b * T_ + t];
  int p = pos_idx[b * T_ + t];

  float bv = -1e30f; int bi = 0;
#pragma unroll
  for (int sp = 0; sp < SPL; sp++) {
    int o = (b * SPL + sp) * M_ + a;
    float v = g_partMax[o]; int i2 = g_partIdx[o];
    if (v > bv || (v == bv && i2 < bi)) { bv = v; bi = i2; }
  }
  int cg = non_idx[b * NN_ + bi];
  float inv = g_nonInv[b * NN_ + bi];

  const float4* Ar = (const float4*)(g_mucN + ((size_t)b * M_ + a) * D_);
  const float4* Pr = (const float4*)(g_mucN + ((size_t)b * M_ + p) * D_);
  const float4* Nr = (const float4*)(emb + ((size_t)b * C_ + cg) * D_);
  float dp = 0.f, dn = 0.f;
#pragma unroll
  for (int i = 0; i < 4; i++) {
    float4 av = Ar[lane + i * 32], pv = Pr[lane + i * 32], nv = Nr[lane + i * 32];
    float e;
    e = av.x - pv.x + 1e-6f; dp += e * e;
    e = av.y - pv.y + 1e-6f; dp += e * e;
    e = av.z - pv.z + 1e-6f; dp += e * e;
    e = av.w - pv.w + 1e-6f; dp += e * e;
    e = av.x - nv.x * inv + 1e-6f; dn += e * e;
    e = av.y - nv.y * inv + 1e-6f; dn += e * e;
    e = av.z - nv.z * inv + 1e-6f; dn += e * e;
    e = av.w - nv.w * inv + 1e-6f; dn += e * e;
  }
#pragma unroll
  for (int d = 16; d; d >>= 1) {
    dp += __shfl_xor_sync(0xffffffffu, dp, d);
    dn += __shfl_xor_sync(0xffffffffu, dn, d);
  }
  if (lane == 0)
    g_trip[trip] = fmaxf(sqrtf(dp) - sqrtf(dn) + 1.0f, 0.0f);
}

// ---------------------------------------------------------------------------
// Kernel 4: deterministic final reduction.
// ---------------------------------------------------------------------------
__global__ void reduce_kernel(float* __restrict__ out) {
  __shared__ float sm[256];
  float s = 0.f;
  for (int i = threadIdx.x; i < B_ * T_; i += 256) s += g_trip[i];
  sm[threadIdx.x] = s;
  __syncthreads();
  for (int d = 128; d; d >>= 1) {
    if (threadIdx.x < d) sm[threadIdx.x] += sm[threadIdx.x + d];
    __syncthreads();
  }
  if (threadIdx.x == 0) out[0] = sm[0] * (1.0f / (float)(B_ * T_));
}

// ---------------------------------------------------------------------------
extern "C" void kernel_launch(void* const* d_in, const int* in_sizes, int n_in,
                              void* d_out, int out_size) {
  const float* emb = (const float*)d_in[0];
  const int* muc = (const int*)d_in[1];
  const int* non = (const int*)d_in[2];
  const int* anc = (const int*)d_in[3];
  const int* pos = (const int*)d_in[4];

  cudaFuncSetAttribute(mine_kernel, cudaFuncAttributeMaxDynamicSharedMemorySize, SMEM_SZ);

  prep_kernel<<<(B_ * M_) / 8, 256>>>(emb, muc);
  mine_kernel<<<dim3(SPL, B_), 256, SMEM_SZ>>>(emb, non);
  loss_kernel<<<(B_ * T_) / 8, 256>>>(emb, non, anc, pos);
  reduce_kernel<<<1, 256>>>((float*)d_out);
}

// round 9
// speedup vs baseline: 1.5677x; 1.5677x over previous
#include <cuda_runtime.h>
#include <cuda_fp16.h>
#include <stdint.h>

// Problem constants
#define B_   64
#define C_   2048
#define D_   512
#define M_   128
#define T_   100
#define NN_  1920
#define SPL  2          // splits of the non-muc rows per batch (128 CTAs = 1 wave)
#define RPS  960        // rows per split
#define TR   16         // non rows per tile
#define NT   60         // tiles per split

// Scratch (device globals; no allocation allowed)
__device__ __align__(16) __half g_mucH[(size_t)B_ * M_ * D_];    // RAW muc rows, fp16 (GEMM operand)
__device__ __align__(16) float  g_mucN[(size_t)B_ * M_ * D_];    // normalized muc rows, fp32 (loss)
__device__ float g_nonInv[B_ * NN_];                             // 1/max(||raw non row||,1e-12)
__device__ float g_partMax[B_ * SPL * M_];
__device__ int   g_partIdx[B_ * SPL * M_];
__device__ float g_trip[B_ * T_];

// ---------------------------------------------------------------------------
// Kernel 1: muc-only gather. One warp per (b, j) muc row.
// ---------------------------------------------------------------------------
__global__ void __launch_bounds__(256) prep_kernel(const float* __restrict__ emb,
                                                   const int* __restrict__ muc_idx) {
  int lane = threadIdx.x & 31;
  int r = blockIdx.x * 8 + (threadIdx.x >> 5);   // [0, B_*M_)
  int b = r >> 7;
  int j = r & 127;
  int src = muc_idx[b * M_ + j];

  const float4* p = (const float4*)(emb + ((size_t)b * C_ + src) * D_);
  float4 v[4];
  float ss = 0.f;
#pragma unroll
  for (int i = 0; i < 4; i++) {
    v[i] = p[lane + i * 32];
    ss += v[i].x * v[i].x + v[i].y * v[i].y + v[i].z * v[i].z + v[i].w * v[i].w;
  }
#pragma unroll
  for (int d = 16; d; d >>= 1) ss += __shfl_xor_sync(0xffffffffu, ss, d);
  float inv = 1.0f / fmaxf(sqrtf(ss), 1e-12f);

  float4* dn = (float4*)(g_mucN + ((size_t)b * M_ + j) * D_);
  uint2*  dh = (uint2*)(g_mucH + ((size_t)b * M_ + j) * D_);
#pragma unroll
  for (int i = 0; i < 4; i++) {
    float4 w = v[i];
    __half2 h0 = __floats2half2_rn(w.x, w.y);
    __half2 h1 = __floats2half2_rn(w.z, w.w);
    uint2 u; u.x = *(unsigned*)&h0; u.y = *(unsigned*)&h1;
    dh[lane + i * 32] = u;                    // raw fp16 (anchor norm is argmax-invariant)
    w.x *= inv; w.y *= inv; w.z *= inv; w.w *= inv;
    dn[lane + i * 32] = w;                    // normalized fp32 for the loss
  }
}

// ---------------------------------------------------------------------------
// Kernel 2: fused gather + normalize + GEMM + argmax hard-negative mining.
// Raw fp32 non rows gathered with LDG.128 into REGISTERS (not cp.async),
// norms computed in-register, fp16 converted in-register, STS to swizzled
// smem double buffer. Registers hold tile t+1 while MMA runs on tile t.
// ---------------------------------------------------------------------------
__device__ __forceinline__ uint32_t swz(uint32_t base, int row, int chunk) {
  // fp16 row stride = 1024B; 16B chunks xor-swizzled by row%8
  return base + (uint32_t)(row << 10) + (uint32_t)(((chunk ^ (row & 7)) << 4));
}

__device__ __forceinline__ void cpasync16(uint32_t dst, const void* src) {
  asm volatile("cp.async.cg.shared.global [%0], [%1], 16;\n"
               :: "r"(dst), "l"(__cvta_generic_to_global(src)) : "memory");
}

__device__ __forceinline__ void ldsm4(uint32_t* r, uint32_t addr) {
  asm volatile("ldmatrix.sync.aligned.m8n8.x4.shared.b16 {%0,%1,%2,%3}, [%4];\n"
               : "=r"(r[0]), "=r"(r[1]), "=r"(r[2]), "=r"(r[3]) : "r"(addr));
}

__device__ __forceinline__ void mma16816(float* c, const uint32_t* a, uint32_t b0, uint32_t b1) {
  asm volatile("mma.sync.aligned.m16n8k16.row.col.f32.f16.f16.f32 "
               "{%0,%1,%2,%3}, {%4,%5,%6,%7}, {%8,%9}, {%0,%1,%2,%3};\n"
               : "+f"(c[0]), "+f"(c[1]), "+f"(c[2]), "+f"(c[3])
               : "r"(a[0]), "r"(a[1]), "r"(a[2]), "r"(a[3]), "r"(b0), "r"(b1));
}

// SMEM layout (bytes):
//   sA   : 0      .. 131072   anchors fp16 (128 x 512, swizzled)
//   sH   : 131072 .. 163840   fp16 tile double-buffer (2 x 16 x 1024B, swizzled)
//   sInv : 163840 .. 163968   invn per tile row (2 x 16 floats)
#define OFF_H   131072u
#define OFF_INV 163840u
#define SMEM_SZ 163968

__global__ void __launch_bounds__(256, 1) mine_kernel(const float* __restrict__ emb,
                                                      const int* __restrict__ non_idx) {
  extern __shared__ char smem[];
  uint32_t sbase = (uint32_t)__cvta_generic_to_shared(smem);
  const uint32_t sA = sbase;

  int s = blockIdx.x, b = blockIdx.y;
  int tid = threadIdx.x, lane = tid & 31, w = tid >> 5;
  const __half* gA = g_mucH + (size_t)b * M_ * D_;
  const int* nidx = non_idx + b * NN_ + s * RPS;
  float* sInvF = (float*)(smem + OFF_INV);
  const float* embB = emb + (size_t)b * C_ * D_;

  const int row0 = w * 2;          // this warp's two rows within each tile
  const int row1 = w * 2 + 1;

  // ---- prologue: anchors via cp.async; tile0 rows into registers ----
#pragma unroll
  for (int i = 0; i < 32; i++) {
    int idx = tid + i * 256, row = idx >> 6, c = idx & 63;
    cpasync16(swz(sA, row, c), gA + (size_t)row * D_ + c * 8);
  }
  asm volatile("cp.async.commit_group;\n" ::: "memory");

  int i0 = nidx[row0], i1 = nidx[row1];
  float4 v0[4], v1[4];
  {
    const float4* p0 = (const float4*)(embB + (size_t)i0 * D_);
    const float4* p1 = (const float4*)(embB + (size_t)i1 * D_);
#pragma unroll
    for (int i = 0; i < 4; i++) { v0[i] = p0[lane + i * 32]; v1[i] = p1[lane + i * 32]; }
  }
  i0 = nidx[TR + row0]; i1 = nidx[TR + row1];   // indices for tile 1

  float bv0 = -1e30f, bv1 = -1e30f;
  int bi0 = 0, bi1 = 0;

  const int arow = w * 16 + (lane & 15);
  const int brow = ((lane >> 4) << 3) + (lane & 7);
  const int bsel = (lane >> 3) & 1;

  for (int tile = 0; tile < NT; tile++) {
    int buf = tile & 1;
    uint32_t hB = sbase + OFF_H + (uint32_t)(buf * 16384);

    // ---- convert registers (tile t) -> fp16 smem (swizzled); norms ----
    {
      float ss0 = 0.f, ss1 = 0.f;
#pragma unroll
      for (int i = 0; i < 4; i++) {
        ss0 += v0[i].x * v0[i].x + v0[i].y * v0[i].y + v0[i].z * v0[i].z + v0[i].w * v0[i].w;
        ss1 += v1[i].x * v1[i].x + v1[i].y * v1[i].y + v1[i].z * v1[i].z + v1[i].w * v1[i].w;
      }
#pragma unroll
      for (int i = 0; i < 4; i++) {
        __half2 a0 = __floats2half2_rn(v0[i].x, v0[i].y);
        __half2 a1 = __floats2half2_rn(v0[i].z, v0[i].w);
        uint2 u; u.x = *(unsigned*)&a0; u.y = *(unsigned*)&a1;
        int chunk = (lane >> 1) + i * 16;
        *(uint2*)(smem + (swz(hB, row0, chunk) - sbase) + (lane & 1) * 8) = u;
        __half2 b0h = __floats2half2_rn(v1[i].x, v1[i].y);
        __half2 b1h = __floats2half2_rn(v1[i].z, v1[i].w);
        uint2 u2; u2.x = *(unsigned*)&b0h; u2.y = *(unsigned*)&b1h;
        *(uint2*)(smem + (swz(hB, row1, chunk) - sbase) + (lane & 1) * 8) = u2;
      }
#pragma unroll
      for (int d = 16; d; d >>= 1) {
        ss0 += __shfl_xor_sync(0xffffffffu, ss0, d);
        ss1 += __shfl_xor_sync(0xffffffffu, ss1, d);
      }
      if (lane == 0) {
        float inva = 1.0f / fmaxf(sqrtf(ss0), 1e-12f);
        float invb = 1.0f / fmaxf(sqrtf(ss1), 1e-12f);
        sInvF[buf * 16 + row0] = inva;
        sInvF[buf * 16 + row1] = invb;
        g_nonInv[b * NN_ + s * RPS + tile * TR + row0] = inva;
        g_nonInv[b * NN_ + s * RPS + tile * TR + row1] = invb;
      }
    }
    if (tile == 0) asm volatile("cp.async.wait_group 0;\n" ::: "memory");  // anchors
    __syncthreads();

    // ---- prefetch tile t+1 into registers (hidden under the MMA below) ----
    if (tile + 1 < NT) {
      const float4* p0 = (const float4*)(embB + (size_t)i0 * D_);
      const float4* p1 = (const float4*)(embB + (size_t)i1 * D_);
#pragma unroll
      for (int i = 0; i < 4; i++) { v0[i] = p0[lane + i * 32]; v1[i] = p1[lane + i * 32]; }
      if (tile + 2 < NT) { i0 = nidx[(tile + 2) * TR + row0]; i1 = nidx[(tile + 2) * TR + row1]; }
    }

    // ---- MMA: 128 anchors x 16 non rows x K=512 ----
    float acc[8];
#pragma unroll
    for (int i = 0; i < 8; i++) acc[i] = 0.f;
#pragma unroll
    for (int ks = 0; ks < 32; ks++) {
      uint32_t a[4], bf[4];
      ldsm4(a,  swz(sA, arow, ks * 2 + (lane >> 4)));
      ldsm4(bf, swz(hB, brow, ks * 2 + bsel));
      mma16816(acc + 0, a, bf[0], bf[1]);   // cols 0..7
      mma16816(acc + 4, a, bf[2], bf[3]);   // cols 8..15
    }

    // ---- scale by invn and fold into running argmax ----
    int colBase = s * RPS + tile * TR + ((lane & 3) << 1);
#pragma unroll
    for (int f = 0; f < 2; f++) {
      int cl = f * 8 + ((lane & 3) << 1);           // column within tile
      float ia = sInvF[buf * 16 + cl];
      float ib = sInvF[buf * 16 + cl + 1];
      int c = colBase + f * 8;
      float v;
      v = acc[f * 4 + 0] * ia; if (v > bv0 || (v == bv0 && c     < bi0)) { bv0 = v; bi0 = c; }
      v = acc[f * 4 + 1] * ib; if (v > bv0 || (v == bv0 && c + 1 < bi0)) { bv0 = v; bi0 = c + 1; }
      v = acc[f * 4 + 2] * ia; if (v > bv1 || (v == bv1 && c     < bi1)) { bv1 = v; bi1 = c; }
      v = acc[f * 4 + 3] * ib; if (v > bv1 || (v == bv1 && c + 1 < bi1)) { bv1 = v; bi1 = c + 1; }
    }
  }

  // Combine the 4 lanes that share each output row
#pragma unroll
  for (int d = 1; d < 4; d <<= 1) {
    float ov = __shfl_xor_sync(0xffffffffu, bv0, d);
    int   oi = __shfl_xor_sync(0xffffffffu, bi0, d);
    if (ov > bv0 || (ov == bv0 && oi < bi0)) { bv0 = ov; bi0 = oi; }
    ov = __shfl_xor_sync(0xffffffffu, bv1, d);
    oi = __shfl_xor_sync(0xffffffffu, bi1, d);
    if (ov > bv1 || (ov == bv1 && oi < bi1)) { bv1 = ov; bi1 = oi; }
  }
  if ((lane & 3) == 0) {
    int g = lane >> 2;
    int o = (b * SPL + s) * M_ + w * 16 + g;
    g_partMax[o] = bv0; g_partIdx[o] = bi0;
    g_partMax[o + 8] = bv1; g_partIdx[o + 8] = bi1;
  }
}

// ---------------------------------------------------------------------------
// Kernel 3: per-triplet loss. One warp per (b, t).
// ---------------------------------------------------------------------------
__global__ void __launch_bounds__(256) loss_kernel(const float* __restrict__ emb,
                                                   const int* __restrict__ non_idx,
                                                   const int* __restrict__ anchor_idx,
                                                   const int* __restrict__ pos_idx) {
  int lane = threadIdx.x & 31;
  int trip = blockIdx.x * 8 + (threadIdx.x >> 5);  // [0, B_*T_)
  int b = trip / T_, t = trip - b * T_;
  int a = anchor_idx[b * T_ + t];
  int p = pos_idx[b * T_ + t];

  float bv = -1e30f; int bi = 0;
#pragma unroll
  for (int sp = 0; sp < SPL; sp++) {
    int o = (b * SPL + sp) * M_ + a;
    float v = g_partMax[o]; int i2 = g_partIdx[o];
    if (v > bv || (v == bv && i2 < bi)) { bv = v; bi = i2; }
  }
  int cg = non_idx[b * NN_ + bi];
  float inv = g_nonInv[b * NN_ + bi];

  const float4* Ar = (const float4*)(g_mucN + ((size_t)b * M_ + a) * D_);
  const float4* Pr = (const float4*)(g_mucN + ((size_t)b * M_ + p) * D_);
  const float4* Nr = (const float4*)(emb + ((size_t)b * C_ + cg) * D_);
  float dp = 0.f, dn = 0.f;
#pragma unroll
  for (int i = 0; i < 4; i++) {
    float4 av = Ar[lane + i * 32], pv = Pr[lane + i * 32], nv = Nr[lane + i * 32];
    float e;
    e = av.x - pv.x + 1e-6f; dp += e * e;
    e = av.y - pv.y + 1e-6f; dp += e * e;
    e = av.z - pv.z + 1e-6f; dp += e * e;
    e = av.w - pv.w + 1e-6f; dp += e * e;
    e = av.x - nv.x * inv + 1e-6f; dn += e * e;
    e = av.y - nv.y * inv + 1e-6f; dn += e * e;
    e = av.z - nv.z * inv + 1e-6f; dn += e * e;
    e = av.w - nv.w * inv + 1e-6f; dn += e * e;
  }
#pragma unroll
  for (int d = 16; d; d >>= 1) {
    dp += __shfl_xor_sync(0xffffffffu, dp, d);
    dn += __shfl_xor_sync(0xffffffffu, dn, d);
  }
  if (lane == 0)
    g_trip[trip] = fmaxf(sqrtf(dp) - sqrtf(dn) + 1.0f, 0.0f);
}

// ---------------------------------------------------------------------------
// Kernel 4: deterministic final reduction.
// ---------------------------------------------------------------------------
__global__ void reduce_kernel(float* __restrict__ out) {
  __shared__ float sm[256];
  float s = 0.f;
  for (int i = threadIdx.x; i < B_ * T_; i += 256) s += g_trip[i];
  sm[threadIdx.x] = s;
  __syncthreads();
  for (int d = 128; d; d >>= 1) {
    if (threadIdx.x < d) sm[threadIdx.x] += sm[threadIdx.x + d];
    __syncthreads();
  }
  if (threadIdx.x == 0) out[0] = sm[0] * (1.0f / (float)(B_ * T_));
}

// ---------------------------------------------------------------------------
extern "C" void kernel_launch(void* const* d_in, const int* in_sizes, int n_in,
                              void* d_out, int out_size) {
  const float* emb = (const float*)d_in[0];
  const int* muc = (const int*)d_in[1];
  const int* non = (const int*)d_in[2];
  const int* anc = (const int*)d_in[3];
  const int* pos = (const int*)d_in[4];

  cudaFuncSetAttribute(mine_kernel, cudaFuncAttributeMaxDynamicSharedMemorySize, SMEM_SZ);

  prep_kernel<<<(B_ * M_) / 8, 256>>>(emb, muc);
  mine_kernel<<<dim3(SPL, B_), 256, SMEM_SZ>>>(emb, non);
  loss_kernel<<<(B_ * T_) / 8, 256>>>(emb, non, anc, pos);
  reduce_kernel<<<1, 256>>>((float*)d_out);
}